// round 1
// baseline (speedup 1.0000x reference)
#include <cuda_runtime.h>
#include <cuda_bf16.h>
#include <cstdint>

// Problem constants
#define NB    32
#define CC    64
#define HH    64
#define WW    64
#define HWSZ  4096        // H*W
#define NTOK  131072      // B*H*W
#define KCOD  512
#define DECAYF 0.99f
#define OMDF   0.01f      // f32(1.0 - 0.99) == 0.01f
#define EPSF   1e-5f

// Output layout (concatenated reference outputs, all float32)
#define OUT_ELEMS  8388608            // 32*64*64*64
#define LOSS_OFF   8388608
#define UNIQ_OFF   8388609
#define CB_OFF     8388610

// -------- device scratch (no allocation allowed) --------
__device__ float g_q[KCOD];          // 0.5 * |e_k|^2
__device__ int   g_idx[NTOK];
__device__ float g_counts[KCOD];
__device__ float g_sums[KCOD * CC];
__device__ float g_loss;

// -------- helpers --------
__device__ __forceinline__ void fma2(unsigned long long &acc,
                                     unsigned long long a,
                                     unsigned long long b) {
    // packed 2x fp32 FMA (Blackwell f32x2 pipe): acc = a*b + acc
    asm("fma.rn.f32x2 %0, %1, %2, %0;" : "+l"(acc) : "l"(a), "l"(b));
}

__device__ __forceinline__ float pairsum(unsigned long long v) {
    float lo = __uint_as_float((unsigned)(v & 0xffffffffULL));
    float hi = __uint_as_float((unsigned)(v >> 32));
    return lo + hi;
}

__device__ __forceinline__ float warp_red(float v) {
    #pragma unroll
    for (int o = 16; o; o >>= 1) v += __shfl_xor_sync(0xffffffffu, v, o);
    return v;
}

// ============================================================
// Kernel 0: zero accumulators + precompute q[k] = 0.5*|e_k|^2
// grid 64 x 512
// ============================================================
__global__ void k_prep(const float* __restrict__ cb) {
    int flat = blockIdx.x * 512 + threadIdx.x;   // 0..32767
    if (flat < KCOD * CC) g_sums[flat] = 0.0f;
    if (flat < KCOD) {
        g_counts[flat] = 0.0f;
        const float* r = cb + flat * CC;
        float s = 0.0f;
        #pragma unroll
        for (int c = 0; c < CC; c += 4) {
            float4 v = *(const float4*)(r + c);
            s += v.x*v.x + v.y*v.y + v.z*v.z + v.w*v.w;
        }
        g_q[flat] = 0.5f * s;
    }
    if (flat == 0) g_loss = 0.0f;
}

// ============================================================
// Kernel 1: distances + argmin + quantized output + loss partial
// 512 CTAs x 128 threads, 256 tokens/CTA, codebook chunked 4x128
// smem: xs 64KB (float4 [c4][token]) + es 32KB (float4 [c4][k]) + qs 512B
// ============================================================
#define TOK_PER_CTA 256
#define KCHUNK      128
#define SMEM_ASSIGN ((16*256*4 + 16*128*4 + 128) * 4)   // 98816 B

__global__ __launch_bounds__(128, 2)
void k_assign(const float* __restrict__ x,
              const float* __restrict__ cb,
              float* __restrict__ out) {
    extern __shared__ float smem[];
    float* xs = smem;                  // 16384 floats  (16 c4 * 256 tok * 4)
    float* es = xs + 16 * 256 * 4;     // 8192 floats   (16 c4 * 128 k * 4)
    float* qs = es + 16 * 128 * 4;     // 128 floats
    __shared__ float red[4];

    const int tid = threadIdx.x;
    const int t0  = blockIdx.x * TOK_PER_CTA;
    const int b   = t0 >> 12;          // t0 / 4096
    const int p0  = t0 & 4095;
    const float* xb = x + (size_t)b * CC * HWSZ + p0;

    // load x tile, transpose to xs4[c4][token] (float4 over c)
    for (int i = tid; i < 64 * 64; i += 128) {       // 4096 float4-of-tokens
        int c  = i >> 6;
        int tq = i & 63;                              // token quad
        float4 v = *(const float4*)(xb + c * HWSZ + tq * 4);
        int c4 = c >> 2, cr = c & 3;
        float* dst = xs + c4 * 1024 + cr;
        dst[(tq*4 + 0) * 4] = v.x;
        dst[(tq*4 + 1) * 4] = v.y;
        dst[(tq*4 + 2) * 4] = v.z;
        dst[(tq*4 + 3) * 4] = v.w;
    }
    __syncthreads();

    // per-thread tokens: tid and tid+128
    const float4* xs4 = (const float4*)xs;
    float xsq[2];
    #pragma unroll
    for (int j = 0; j < 2; ++j) {
        int tok = tid + j * 128;
        float s = 0.0f;
        #pragma unroll
        for (int c4 = 0; c4 < 16; ++c4) {
            float4 v = xs4[c4 * 256 + tok];
            s += v.x*v.x + v.y*v.y + v.z*v.z + v.w*v.w;
        }
        xsq[j] = s;
    }

    float best[2] = {3.4e38f, 3.4e38f};
    int   bi[2]   = {0, 0};

    for (int ch = 0; ch < KCOD / KCHUNK; ++ch) {
        __syncthreads();   // protect es from previous chunk's readers
        const int kb = ch * KCHUNK;
        for (int i = tid; i < KCHUNK * 16; i += 128) {
            int k = i >> 4, c4 = i & 15;
            ((float4*)es)[c4 * 128 + k] = ((const float4*)cb)[(kb + k) * 16 + c4];
        }
        if (tid < KCHUNK) qs[tid] = g_q[kb + tid];
        __syncthreads();

        const ulonglong2* es2 = (const ulonglong2*)es;
        const ulonglong2* xs2 = (const ulonglong2*)xs;

        for (int k0 = 0; k0 < KCHUNK; k0 += 8) {
            unsigned long long acc[2][8];
            #pragma unroll
            for (int t = 0; t < 2; ++t)
                #pragma unroll
                for (int kk = 0; kk < 8; ++kk) acc[t][kk] = 0ULL;

            #pragma unroll
            for (int c4 = 0; c4 < 16; ++c4) {
                ulonglong2 e[8];
                #pragma unroll
                for (int kk = 0; kk < 8; ++kk) e[kk] = es2[c4 * 128 + k0 + kk];
                ulonglong2 xa = xs2[c4 * 256 + tid];
                ulonglong2 xc = xs2[c4 * 256 + tid + 128];
                #pragma unroll
                for (int kk = 0; kk < 8; ++kk) {
                    fma2(acc[0][kk], xa.x, e[kk].x);
                    fma2(acc[0][kk], xa.y, e[kk].y);
                    fma2(acc[1][kk], xc.x, e[kk].x);
                    fma2(acc[1][kk], xc.y, e[kk].y);
                }
            }
            #pragma unroll
            for (int kk = 0; kk < 8; ++kk) {
                float q = qs[k0 + kk];
                float d0 = q - pairsum(acc[0][kk]);
                float d1 = q - pairsum(acc[1][kk]);
                if (d0 < best[0]) { best[0] = d0; bi[0] = kb + k0 + kk; }
                if (d1 < best[1]) { best[1] = d1; bi[1] = kb + k0 + kk; }
            }
        }
    }

    // indices out
    g_idx[t0 + tid]       = bi[0];
    g_idx[t0 + 128 + tid] = bi[1];

    // commitment loss partial: |x-e|^2 = |x|^2 + 2*(0.5|e|^2 - x.e)
    float lsum = (xsq[0] + 2.0f * best[0]) + (xsq[1] + 2.0f * best[1]);
    lsum = warp_red(lsum);
    if ((tid & 31) == 0) red[tid >> 5] = lsum;
    __syncthreads();
    if (tid == 0) atomicAdd(&g_loss, red[0] + red[1] + red[2] + red[3]);

    // quantized output: out[b, c, p] = cb[bi][c]  (coalesced across tid)
    float* ob = out + (size_t)b * CC * HWSZ + p0;
    const float* r0 = cb + (size_t)bi[0] * CC;
    const float* r1 = cb + (size_t)bi[1] * CC;
    #pragma unroll 8
    for (int c = 0; c < CC; ++c) {
        ob[c * HWSZ + tid]       = __ldg(r0 + c);
        ob[c * HWSZ + tid + 128] = __ldg(r1 + c);
    }
}

// ============================================================
// Kernel 2: segment sums + counts (smem staging, padded stride 65)
// 64 CTAs x 256 threads, 2048 tokens/CTA
// ============================================================
#define SMEM_SEG ((512*65 + 512) * 4 + 2048 * 4)   // 143360 B

__global__ __launch_bounds__(256)
void k_segsum(const float* __restrict__ x) {
    extern __shared__ float sm2[];
    float* ssum = sm2;                  // 512*65
    float* scnt = ssum + 512 * 65;      // 512
    int*   sid  = (int*)(scnt + 512);   // 2048

    const int tid = threadIdx.x;
    const int t0  = blockIdx.x * 2048;
    const int b   = t0 >> 12;
    const int p0  = t0 & 4095;
    const float* xb = x + (size_t)b * CC * HWSZ + p0;

    for (int i = tid; i < 512 * 65; i += 256) ssum[i] = 0.0f;
    for (int i = tid; i < 512;      i += 256) scnt[i] = 0.0f;
    for (int i = tid; i < 2048;     i += 256) sid[i]  = g_idx[t0 + i];
    __syncthreads();

    for (int i = tid; i < 2048; i += 256) atomicAdd(&scnt[sid[i]], 1.0f);

    const int cg = tid >> 6;      // 0..3
    const int tk = tid & 63;
    #pragma unroll 4
    for (int co = 0; co < 16; ++co) {
        int c = co * 4 + cg;
        const float* xc = xb + c * HWSZ;
        for (int tb = 0; tb < 2048; tb += 64) {
            int tl = tb + tk;
            float v = xc[tl];
            atomicAdd(&ssum[sid[tl] * 65 + c], v);
        }
    }
    __syncthreads();

    for (int i = tid; i < KCOD * CC; i += 256) {
        int k = i >> 6, c = i & 63;
        atomicAdd(&g_sums[i], ssum[k * 65 + c]);
    }
    for (int i = tid; i < KCOD; i += 256) atomicAdd(&g_counts[i], scnt[i]);
}

// ============================================================
// Kernel 3: EMA update, smoothing, new codebook, scalars
// single CTA, 512 threads
// ============================================================
__global__ __launch_bounds__(512)
void k_final(const float* __restrict__ ema_cs,
             const float* __restrict__ ema_w,
             float* __restrict__ out) {
    __shared__ float sm[KCOD];
    __shared__ float rn[16], ru[16];
    __shared__ float s_n, s_u;

    const int k = threadIdx.x;
    float cnt = g_counts[k];
    float ncs = DECAYF * ema_cs[k] + OMDF * cnt;

    float nv = warp_red(ncs);
    float uv = warp_red(cnt > 0.0f ? 1.0f : 0.0f);
    if ((k & 31) == 0) { rn[k >> 5] = nv; ru[k >> 5] = uv; }
    __syncthreads();
    if (k == 0) {
        float a = 0.0f, u = 0.0f;
        #pragma unroll
        for (int i = 0; i < 16; ++i) { a += rn[i]; u += ru[i]; }
        s_n = a; s_u = u;
    }
    __syncthreads();

    float smoothed = (ncs + EPSF) / (s_n + (float)KCOD * EPSF) * s_n;
    sm[k] = smoothed;
    __syncthreads();

    for (int i = k; i < KCOD * CC; i += 512) {
        float nw = DECAYF * ema_w[i] + OMDF * g_sums[i];
        out[CB_OFF + i] = nw / sm[i >> 6];
    }
    if (k == 0) {
        out[LOSS_OFF] = g_loss * (1.0f / (float)OUT_ELEMS);
        out[UNIQ_OFF] = s_u;
    }
}

// ============================================================
extern "C" void kernel_launch(void* const* d_in, const int* in_sizes, int n_in,
                              void* d_out, int out_size) {
    const float* x   = (const float*)d_in[0];
    const float* cb  = (const float*)d_in[1];
    const float* ecs = (const float*)d_in[2];
    const float* ew  = (const float*)d_in[3];
    float* out = (float*)d_out;

    cudaFuncSetAttribute(k_assign, cudaFuncAttributeMaxDynamicSharedMemorySize, SMEM_ASSIGN);
    cudaFuncSetAttribute(k_segsum, cudaFuncAttributeMaxDynamicSharedMemorySize, SMEM_SEG);

    k_prep<<<64, 512>>>(cb);
    k_assign<<<NTOK / TOK_PER_CTA, 128, SMEM_ASSIGN>>>(x, cb, out);
    k_segsum<<<NTOK / 2048, 256, SMEM_SEG>>>(x);
    k_final<<<1, 512>>>(ecs, ew, out);
}

// round 2
// speedup vs baseline: 1.3588x; 1.3588x over previous
#include <cuda_runtime.h>
#include <cuda_bf16.h>
#include <cstdint>

// Problem constants
#define CC    64
#define HWSZ  4096
#define NTOK  131072
#define KCOD  512
#define EPSF  1e-5f

// Output layout (concatenated reference outputs, all float32)
#define OUT_ELEMS  8388608
#define LOSS_OFF   8388608
#define UNIQ_OFF   8388609
#define CB_OFF     8388610

// -------- device scratch --------
__device__ float g_counts[KCOD];
__device__ float g_sums[KCOD * CC];
__device__ float g_loss;

// -------- helpers --------
__device__ __forceinline__ void fma2(unsigned long long &acc,
                                     unsigned long long a,
                                     unsigned long long b) {
    asm("fma.rn.f32x2 %0, %1, %2, %0;" : "+l"(acc) : "l"(a), "l"(b));
}
__device__ __forceinline__ unsigned long long packf2(float a, float b) {
    unsigned long long r;
    asm("mov.b64 %0, {%1, %2};" : "=l"(r) : "f"(a), "f"(b));
    return r;
}
__device__ __forceinline__ float pairsum(unsigned long long v) {
    float lo, hi;
    asm("mov.b64 {%0, %1}, %2;" : "=f"(lo), "=f"(hi) : "l"(v));
    return lo + hi;
}
__device__ __forceinline__ void red4(float* p, float a, float b, float c, float d) {
    asm volatile("red.global.add.v4.f32 [%0], {%1, %2, %3, %4};"
                 :: "l"(p), "f"(a), "f"(b), "f"(c), "f"(d) : "memory");
}
__device__ __forceinline__ float warp_red(float v) {
    #pragma unroll
    for (int o = 16; o; o >>= 1) v += __shfl_xor_sync(0xffffffffu, v, o);
    return v;
}

// ============================================================
// Kernel 0: zero accumulators
// ============================================================
__global__ void k_zero() {
    int i = blockIdx.x * 512 + threadIdx.x;
    if (i < KCOD * CC) g_sums[i] = 0.0f;
    if (i < KCOD)      g_counts[i] = 0.0f;
    if (i == 0)        g_loss = 0.0f;
}

// ============================================================
// Kernel 1: fused assign + quantized output + loss + counts/sums
// 512 CTAs x 256 threads, 1 token/thread (x in registers),
// full codebook resident in smem (128KB) + q (2KB). 1 CTA/SM.
// ============================================================
#define SMEM_ASSIGN (KCOD * CC * 4 + KCOD * 4)   // 133120 B

__global__ __launch_bounds__(256, 1)
void k_assign(const float* __restrict__ x,
              const float* __restrict__ cb,
              float* __restrict__ out) {
    extern __shared__ float smem[];
    float* es = smem;               // [512][64]
    float* qs = es + KCOD * CC;     // [512]
    __shared__ float red_s[8];

    const int tid  = threadIdx.x;
    const int lane = tid & 31;

    // ---- load full codebook to smem (coalesced float4) ----
    float4* es4 = (float4*)es;
    const float4* cb4 = (const float4*)cb;
    #pragma unroll
    for (int i = 0; i < 32; ++i)            // 32 * 256 = 8192 float4
        es4[i * 256 + tid] = cb4[i * 256 + tid];
    __syncthreads();

    // ---- q[k] = 0.5*|e_k|^2  (rotated reads to dodge bank degeneracy) ----
    #pragma unroll
    for (int r = 0; r < 2; ++r) {
        int k = tid + r * 256;
        const float4* row = (const float4*)(es + k * CC);
        float s = 0.0f;
        #pragma unroll
        for (int j = 0; j < 16; ++j) {
            float4 v = row[(j + lane) & 15];
            s += v.x*v.x + v.y*v.y + v.z*v.z + v.w*v.w;
        }
        qs[k] = 0.5f * s;
    }
    __syncthreads();

    // ---- load this thread's token x into registers (coalesced) ----
    const int blk = blockIdx.x;
    const int b   = blk >> 4;                       // 16 CTAs per image
    const int p   = ((blk & 15) << 8) + tid;        // position within H*W
    const float* xb = x + ((size_t)b << 18) + p;    // b*64*4096 + p

    float xr[64];
    #pragma unroll
    for (int c = 0; c < 64; ++c) xr[c] = xb[(size_t)c << 12];

    unsigned long long xp[32];
    float xsq = 0.0f;
    #pragma unroll
    for (int i = 0; i < 32; ++i) {
        float a = xr[2*i], bq = xr[2*i+1];
        xsq += a*a + bq*bq;
        xp[i] = packf2(a, bq);
    }

    // ---- mainloop: 512 codes, 8-code register tile ----
    float best = 3.4e38f;
    int   bi   = 0;
    const ulonglong2* es2 = (const ulonglong2*)es;  // 16 per row

    for (int k0 = 0; k0 < KCOD; k0 += 8) {
        unsigned long long acc[8];
        #pragma unroll
        for (int kk = 0; kk < 8; ++kk) acc[kk] = 0ULL;

        #pragma unroll
        for (int c4 = 0; c4 < 16; ++c4) {
            ulonglong2 e[8];
            #pragma unroll
            for (int kk = 0; kk < 8; ++kk)
                e[kk] = es2[(k0 + kk) * 16 + c4];   // warp-broadcast LDS.128
            #pragma unroll
            for (int kk = 0; kk < 8; ++kk) {
                fma2(acc[kk], xp[2*c4],     e[kk].x);
                fma2(acc[kk], xp[2*c4 + 1], e[kk].y);
            }
        }
        #pragma unroll
        for (int kk = 0; kk < 8; ++kk) {
            float d = qs[k0 + kk] - pairsum(acc[kk]);
            if (d < best) { best = d; bi = k0 + kk; }   // strict < keeps first min
        }
    }

    // ---- commitment loss partial: |x-e|^2 = |x|^2 + 2*best ----
    float lsum = warp_red(xsq + 2.0f * best);
    if (lane == 0) red_s[tid >> 5] = lsum;
    __syncthreads();
    if (tid == 0) {
        float a = 0.0f;
        #pragma unroll
        for (int i = 0; i < 8; ++i) a += red_s[i];
        atomicAdd(&g_loss, a);
    }

    // ---- counts + segment sums (vector global reductions) ----
    atomicAdd(&g_counts[bi], 1.0f);
    float* srow = g_sums + bi * CC;
    #pragma unroll
    for (int i = 0; i < 16; ++i) {
        float a, b0, c0, d0;
        asm("mov.b64 {%0, %1}, %2;" : "=f"(a),  "=f"(b0) : "l"(xp[2*i]));
        asm("mov.b64 {%0, %1}, %2;" : "=f"(c0), "=f"(d0) : "l"(xp[2*i+1]));
        red4(srow + i * 4, a, b0, c0, d0);
    }

    // ---- quantized output: gather chosen row from smem, coalesced STG ----
    float* ob = out + ((size_t)b << 18) + p;
    const float4* erow = (const float4*)(es + (bi << 6));
    #pragma unroll
    for (int j = 0; j < 16; ++j) {
        float4 v = erow[j];
        ob[(size_t)(4*j + 0) << 12] = v.x;
        ob[(size_t)(4*j + 1) << 12] = v.y;
        ob[(size_t)(4*j + 2) << 12] = v.z;
        ob[(size_t)(4*j + 3) << 12] = v.w;
    }
}

// ============================================================
// Kernel 2: EMA update + smoothing + new codebook + scalars
// grid 64 x 512; each CTA redundantly reduces counts (cheap),
// then writes its 512-element slice of the codebook.
// ============================================================
__global__ __launch_bounds__(512)
void k_final(const float* __restrict__ ema_cs,
             const float* __restrict__ ema_w,
             float* __restrict__ out) {
    __shared__ float sm[KCOD];
    __shared__ float rn[16], ru[16];
    __shared__ float s_n, s_u;

    const int t = threadIdx.x;
    float cnt = g_counts[t];
    float ncs = 0.99f * ema_cs[t] + 0.01f * cnt;

    float nv = warp_red(ncs);
    float uv = warp_red(cnt > 0.0f ? 1.0f : 0.0f);
    if ((t & 31) == 0) { rn[t >> 5] = nv; ru[t >> 5] = uv; }
    __syncthreads();
    if (t == 0) {
        float a = 0.0f, u = 0.0f;
        #pragma unroll
        for (int i = 0; i < 16; ++i) { a += rn[i]; u += ru[i]; }
        s_n = a; s_u = u;
    }
    __syncthreads();

    sm[t] = (ncs + EPSF) / (s_n + (float)KCOD * EPSF) * s_n;
    __syncthreads();

    int i = blockIdx.x * 512 + t;                 // 64 CTAs x 512 = 32768
    float nw = 0.99f * ema_w[i] + 0.01f * g_sums[i];
    out[CB_OFF + i] = nw / sm[i >> 6];

    if (blockIdx.x == 0 && t == 0) {
        out[LOSS_OFF] = g_loss * (1.0f / (float)OUT_ELEMS);
        out[UNIQ_OFF] = s_u;
    }
}

// ============================================================
extern "C" void kernel_launch(void* const* d_in, const int* in_sizes, int n_in,
                              void* d_out, int out_size) {
    const float* x   = (const float*)d_in[0];
    const float* cb  = (const float*)d_in[1];
    const float* ecs = (const float*)d_in[2];
    const float* ew  = (const float*)d_in[3];
    float* out = (float*)d_out;

    cudaFuncSetAttribute(k_assign, cudaFuncAttributeMaxDynamicSharedMemorySize, SMEM_ASSIGN);

    k_zero<<<65, 512>>>();
    k_assign<<<NTOK / 256, 256, SMEM_ASSIGN>>>(x, cb, out);
    k_final<<<64, 512>>>(ecs, ew, out);
}